// round 5
// baseline (speedup 1.0000x reference)
#include <cuda_runtime.h>
#include <cuda_bf16.h>
#include <cuda_fp8.h>
#include <math.h>
#include <cstdint>

// ---------------------------------------------------------------------------
// Problem constants
// ---------------------------------------------------------------------------
#define NROWS 8192       // 4B rows in rep
#define HALF  4096       // rows per input
#define D     512        // embedding dim
#define DB    512        // bytes per row in fp8

// GEMM config: 128x128 CTA tile, K chunked by 128 fp8 (128 B rows), 8 warps
#define TILE    128
#define KC      128                 // fp8 elems per K chunk
#define NCHUNK  (D / KC)            // 4
#define NT      256
#define NSTAGE  3
#define STAGE_B (TILE * KC)         // 16384 bytes per operand per stage
#define SLOT_B  (2 * STAGE_B)       // A + B per stage
#define SMEM_DYN (NSTAGE * SLOT_B)  // 96 KB

#define NTILES  2080                // 64*65/2 upper-triangular 128x128 tiles

// fp8 scale: rows multiplied by 64 before quantization -> dot scaled by 4096.
// exp(2*dot) = fast_exp(acc * 2/4096).
#define ESC (2.0f / 4096.0f)

// ---------------------------------------------------------------------------
// Static scratch
// ---------------------------------------------------------------------------
__device__ __align__(16) uint8_t g_rep8[(size_t)NROWS * DB];  // 4 MB e4m3
__device__ double g_acc[2];        // [0] = S_offdiag (x2), [1] = nominator
__device__ unsigned int g_done;    // CTA arrival counter (self-resetting)

// ---------------------------------------------------------------------------
// Helpers
// ---------------------------------------------------------------------------
__device__ __forceinline__ uint32_t smem_u32(const void* p) {
    uint32_t a;
    asm("{ .reg .u64 t; cvta.to.shared.u64 t, %1; cvt.u32.u64 %0, t; }"
        : "=r"(a) : "l"(p));
    return a;
}

__device__ __forceinline__ void cp16(uint32_t dst, const void* src) {
    asm volatile("cp.async.cg.shared.global [%0], [%1], 16;"
                 :: "r"(dst), "l"(src));
}
#define CP_COMMIT() asm volatile("cp.async.commit_group;" ::: "memory")
#define CP_WAIT(n)  asm volatile("cp.async.wait_group %0;" :: "n"(n) : "memory")

__device__ __forceinline__ void ldmx4(uint32_t& r0, uint32_t& r1,
                                      uint32_t& r2, uint32_t& r3, uint32_t a) {
    asm volatile("ldmatrix.sync.aligned.m8n8.x4.shared.b16 {%0,%1,%2,%3}, [%4];"
                 : "=r"(r0), "=r"(r1), "=r"(r2), "=r"(r3) : "r"(a));
}

// FP8 e4m3 MMA: m16n8k32, fragment layout = bf16 m16n8k16 with b16 -> 2x e4m3
__device__ __forceinline__ void mma16832(float* c, const uint32_t* a,
                                         const uint32_t* b) {
    asm volatile(
        "mma.sync.aligned.m16n8k32.row.col.f32.e4m3.e4m3.f32 "
        "{%0,%1,%2,%3}, {%4,%5,%6,%7}, {%8,%9}, {%0,%1,%2,%3};"
        : "+f"(c[0]), "+f"(c[1]), "+f"(c[2]), "+f"(c[3])
        : "r"(a[0]), "r"(a[1]), "r"(a[2]), "r"(a[3]), "r"(b[0]), "r"(b[1]));
}

// FMA-only exp for x in ~[-2.5, 2.5] (avoids MUFU pipe). Rel err <= ~4e-6.
__device__ __forceinline__ float fast_exp(float x) {
    float t  = x * 1.44269504088896341f;
    float fn = t + 12582912.0f;
    int   m  = __float_as_int(fn) - 0x4B400000;
    float r  = t - (fn - 12582912.0f);
    float p  = 1.3333558146e-3f;
    p = fmaf(p, r, 9.6181291e-3f);
    p = fmaf(p, r, 5.5504108664e-2f);
    p = fmaf(p, r, 2.4022650696e-1f);
    p = fmaf(p, r, 6.9314718056e-1f);
    p = fmaf(p, r, 1.0f);
    return __int_as_float(__float_as_int(p) + (m << 23));
}

// ---------------------------------------------------------------------------
// K1: L2-normalize rows of [emb_i; emb_j], scale by 64, quantize to e4m3.
// One block (128 threads) per row. Block 0 zeroes the accumulators.
// ---------------------------------------------------------------------------
__global__ void normalize_kernel(const float* __restrict__ a,
                                 const float* __restrict__ b) {
    int row = blockIdx.x;
    int tid = threadIdx.x;  // 128
    if (row == 0 && tid == 0) { g_acc[0] = 0.0; g_acc[1] = 0.0; }

    const float* src = (row < HALF) ? (a + (size_t)row * D)
                                    : (b + (size_t)(row - HALF) * D);

    float4 v = reinterpret_cast<const float4*>(src)[tid];
    float ss = v.x * v.x + v.y * v.y + v.z * v.z + v.w * v.w;

    #pragma unroll
    for (int o = 16; o > 0; o >>= 1)
        ss += __shfl_xor_sync(0xFFFFFFFFu, ss, o);

    __shared__ float ws[4];
    int wid = tid >> 5, lane = tid & 31;
    if (lane == 0) ws[wid] = ss;
    __syncthreads();

    float total = ws[0] + ws[1] + ws[2] + ws[3];
    float s = rsqrtf(fmaxf(total, 1e-24f)) * 64.0f;  // normalize + fp8 scale

    __nv_fp8x2_storage_t p0 = __nv_cvt_float2_to_fp8x2(
        make_float2(v.x * s, v.y * s), __NV_SATFINITE, __NV_E4M3);
    __nv_fp8x2_storage_t p1 = __nv_cvt_float2_to_fp8x2(
        make_float2(v.z * s, v.w * s), __NV_SATFINITE, __NV_E4M3);
    uint32_t pk = (uint32_t)p0 | ((uint32_t)p1 << 16);
    reinterpret_cast<uint32_t*>(g_rep8 + (size_t)row * DB)[tid] = pk;
}

// ---------------------------------------------------------------------------
// Stage loader: 128 rows x 128B per operand, 16B chunks, XOR swizzle
// chunk' = chunk ^ (row & 7) — conflict-free for cp.async and ldmatrix.
// ---------------------------------------------------------------------------
__device__ __forceinline__ void load_stage(uint32_t sA, uint32_t sB,
                                           const uint8_t* __restrict__ Ab,
                                           const uint8_t* __restrict__ Bb,
                                           int kk, int tid) {
    #pragma unroll
    for (int s = 0; s < 4; s++) {
        int idx = tid + s * NT;          // 0..1023
        int row = idx >> 3;              // 0..127
        int ch  = idx & 7;               // 16B chunk in 128B row
        uint32_t dst = (uint32_t)(row * 128 + ((ch ^ (row & 7)) << 4));
        cp16(sA + dst, Ab + (size_t)row * DB + kk + ch * 16);
        cp16(sB + dst, Bb + (size_t)row * DB + kk + ch * 16);
    }
}

// ---------------------------------------------------------------------------
// K2: fp8 mma.sync GEMM over the 2080 upper-triangular tiles, fused with
// exp reduction and last-CTA finalize.
// ---------------------------------------------------------------------------
__global__ __launch_bounds__(NT, 2)
void gemm_exp_kernel(float* __restrict__ out) {
    // Decode linear tile index -> (bi, bj), bj >= bi.
    int idx = blockIdx.x;
    int bi  = (int)((129.0f - sqrtf(16641.0f - 8.0f * (float)idx)) * 0.5f);
    if (bi > 63) bi = 63;
    while (bi * (129 - bi) / 2 > idx) bi--;
    while ((bi + 1) * (129 - (bi + 1)) / 2 <= idx) bi++;
    int bj = bi + (idx - bi * (129 - bi) / 2);

    extern __shared__ char sm[];
    uint32_t sbase = smem_u32(sm);

    const int tid    = threadIdx.x;
    const int wid    = tid >> 5;
    const int lane   = tid & 31;
    const int warp_m = wid & 1;      // 2 warps down M (64 rows each)
    const int warp_n = wid >> 1;     // 4 warps across N (32 cols each)

    const uint8_t* __restrict__ Ab = g_rep8 + (size_t)bi * TILE * DB;
    const uint8_t* __restrict__ Bb = g_rep8 + (size_t)bj * TILE * DB;

    float acc[4][4][4];   // [mf][nf][frag]
    #pragma unroll
    for (int mf = 0; mf < 4; mf++)
        #pragma unroll
        for (int nf = 0; nf < 4; nf++)
            #pragma unroll
            for (int e = 0; e < 4; e++)
                acc[mf][nf][e] = 0.0f;

    // Per-lane ldmatrix address components (identical to bf16 case —
    // fp8 k32 fragments are bf16 k16 fragments with b16 -> byte pairs)
    const int a_row = lane & 15;
    const int a_hi  = lane >> 4;
    const int a_sw  = a_row & 7;
    const int b_n   = ((lane >> 4) << 3) + (lane & 7);
    const int b_hi  = (lane >> 3) & 1;
    const int b_sw  = b_n & 7;

    // Prologue: fill first two ring slots
    load_stage(sbase,          sbase + STAGE_B,          Ab, Bb, 0,  tid);
    CP_COMMIT();
    load_stage(sbase + SLOT_B, sbase + SLOT_B + STAGE_B, Ab, Bb, KC, tid);
    CP_COMMIT();

    #pragma unroll 1
    for (int j = 0; j < NCHUNK; j++) {
        if (j < NCHUNK - 1) CP_WAIT(1); else CP_WAIT(0);
        __syncthreads();

        if (j + 2 < NCHUNK) {
            uint32_t sl = sbase + (uint32_t)((j + 2) % NSTAGE) * SLOT_B;
            load_stage(sl, sl + STAGE_B, Ab, Bb, (j + 2) * KC, tid);
            CP_COMMIT();
        }

        uint32_t sA = sbase + (uint32_t)(j % NSTAGE) * SLOT_B;
        uint32_t sB = sA + STAGE_B;

        #pragma unroll
        for (int ks = 0; ks < 4; ks++) {   // 4 x k32 per 128B chunk
            uint32_t afr[4][4];
            #pragma unroll
            for (int mf = 0; mf < 4; mf++) {
                int grow = warp_m * 64 + mf * 16 + a_row;
                uint32_t ca = (uint32_t)((2 * ks + a_hi) ^ a_sw);
                ldmx4(afr[mf][0], afr[mf][1], afr[mf][2], afr[mf][3],
                      sA + grow * 128 + ca * 16);
            }
            uint32_t bfr[4][2];
            #pragma unroll
            for (int np = 0; np < 2; np++) {
                int gn = warp_n * 32 + np * 16 + b_n;
                uint32_t cb = (uint32_t)((2 * ks + b_hi) ^ b_sw);
                uint32_t r0, r1, r2, r3;
                ldmx4(r0, r1, r2, r3, sB + gn * 128 + cb * 16);
                bfr[2 * np][0] = r0; bfr[2 * np][1] = r1;
                bfr[2 * np + 1][0] = r2; bfr[2 * np + 1][1] = r3;
            }
            #pragma unroll
            for (int mf = 0; mf < 4; mf++)
                #pragma unroll
                for (int nf = 0; nf < 4; nf++)
                    mma16832(acc[mf][nf], afr[mf], bfr[nf]);
        }
    }

    // Epilogue: exp(2*dot) = fast_exp(acc * ESC); masked sums from registers.
    const bool diag = (bi == bj);
    const int  dbj  = bj - bi;
    const bool nomt = (dbj == 16) | (dbj == 32) | (dbj == 48);
    const int  grp  = lane >> 2;
    const int  tig  = lane & 3;

    float sum = 0.0f, nom = 0.0f;
    #pragma unroll
    for (int mf = 0; mf < 4; mf++) {
        #pragma unroll
        for (int nf = 0; nf < 4; nf++) {
            int m0 = warp_m * 64 + mf * 16 + grp;
            int n0 = warp_n * 32 + nf * 8 + tig * 2;
            #pragma unroll
            for (int e = 0; e < 4; e++) {
                int mm = m0 + (e >> 1) * 8;
                int nn = n0 + (e & 1);
                float ex = fast_exp(acc[mf][nf][e] * ESC);
                if (!diag || nn > mm) sum += ex;
                if (nomt & (nn == mm)) nom += ex;
            }
        }
    }

    // Block reduction -> one double atomic per tile (reuse stage smem)
    __syncthreads();
    float2* red = reinterpret_cast<float2*>(sm);
    red[tid] = make_float2(sum, nom);
    __syncthreads();
    #pragma unroll
    for (int s2 = NT / 2; s2 >= 32; s2 >>= 1) {
        if (tid < s2) {
            float2 o = red[tid + s2];
            red[tid].x += o.x;
            red[tid].y += o.y;
        }
        __syncthreads();
    }
    if (tid < 32) {
        float2 v2 = red[tid];
        #pragma unroll
        for (int o = 16; o > 0; o >>= 1) {
            v2.x += __shfl_xor_sync(0xFFFFFFFFu, v2.x, o);
            v2.y += __shfl_xor_sync(0xFFFFFFFFu, v2.y, o);
        }
        if (tid == 0) {
            atomicAdd(&g_acc[0], 2.0 * (double)v2.x);   // mirror lower triangle
            if (v2.y != 0.0f) atomicAdd(&g_acc[1], 2.0 * (double)v2.y);

            // Last-CTA finalize
            __threadfence();
            unsigned int t = atomicAdd(&g_done, 1u);
            if (t == NTILES - 1) {
                __threadfence();
                double nomv = g_acc[1];
                double den  = g_acc[0] - nomv;
                out[0] = (float)(-log(nomv / den) / (double)NROWS);
                g_done = 0;   // reset for next graph replay
            }
        }
    }
}

// ---------------------------------------------------------------------------
// Entry point
// ---------------------------------------------------------------------------
extern "C" void kernel_launch(void* const* d_in, const int* in_sizes, int n_in,
                              void* d_out, int out_size) {
    const float* emb_i = (const float*)d_in[0];
    const float* emb_j = (const float*)d_in[1];
    float* out = (float*)d_out;

    cudaFuncSetAttribute(gemm_exp_kernel,
                         cudaFuncAttributeMaxDynamicSharedMemorySize, SMEM_DYN);

    normalize_kernel<<<NROWS, 128>>>(emb_i, emb_j);
    gemm_exp_kernel<<<NTILES, NT, SMEM_DYN>>>(out);
}

// round 6
// speedup vs baseline: 1.0030x; 1.0030x over previous
#include <cuda_runtime.h>
#include <cuda_bf16.h>
#include <math.h>
#include <cstdint>

// ---------------------------------------------------------------------------
// Problem constants
// ---------------------------------------------------------------------------
#define NROWS 8192       // 4B rows in rep
#define HALF  4096       // rows per input
#define D     512        // embedding dim

// GEMM config: 128x256 CTA tile, 8 warps of 64x64, K chunked by 64 bf16
#define TM_CTA  128
#define TN_CTA  256
#define KC      64
#define NCHUNK  (D / KC)             // 8
#define NT      256
#define NSTAGE  4
#define A_B     (TM_CTA * KC * 2)    // 16384 B per A stage
#define B_B     (TN_CTA * KC * 2)    // 32768 B per B stage
#define SLOT_B  (A_B + B_B)          // 48 KB per stage
#define SMEM_DYN (NSTAGE * SLOT_B)   // 192 KB

#define NTILES  1056                 // sum over bi of (32 - bi/2)

// ---------------------------------------------------------------------------
// Static scratch
// ---------------------------------------------------------------------------
__device__ __align__(16) __nv_bfloat16 g_repb[(size_t)NROWS * D];  // 8 MB
__device__ double g_acc[2];        // [0] = S_offdiag (x2), [1] = nominator
__device__ unsigned int g_done;    // CTA arrival counter (self-resetting)

// ---------------------------------------------------------------------------
// Helpers
// ---------------------------------------------------------------------------
__device__ __forceinline__ uint32_t smem_u32(const void* p) {
    uint32_t a;
    asm("{ .reg .u64 t; cvta.to.shared.u64 t, %1; cvt.u32.u64 %0, t; }"
        : "=r"(a) : "l"(p));
    return a;
}

__device__ __forceinline__ void cp16(uint32_t dst, const void* src) {
    asm volatile("cp.async.cg.shared.global [%0], [%1], 16;"
                 :: "r"(dst), "l"(src));
}
#define CP_COMMIT() asm volatile("cp.async.commit_group;" ::: "memory")
#define CP_WAIT(n)  asm volatile("cp.async.wait_group %0;" :: "n"(n) : "memory")

__device__ __forceinline__ void ldmx4(uint32_t& r0, uint32_t& r1,
                                      uint32_t& r2, uint32_t& r3, uint32_t a) {
    asm volatile("ldmatrix.sync.aligned.m8n8.x4.shared.b16 {%0,%1,%2,%3}, [%4];"
                 : "=r"(r0), "=r"(r1), "=r"(r2), "=r"(r3) : "r"(a));
}

__device__ __forceinline__ void mma16816(float* c, const uint32_t* a,
                                         const uint32_t* b) {
    asm volatile(
        "mma.sync.aligned.m16n8k16.row.col.f32.bf16.bf16.f32 "
        "{%0,%1,%2,%3}, {%4,%5,%6,%7}, {%8,%9}, {%0,%1,%2,%3};"
        : "+f"(c[0]), "+f"(c[1]), "+f"(c[2]), "+f"(c[3])
        : "r"(a[0]), "r"(a[1]), "r"(a[2]), "r"(a[3]), "r"(b[0]), "r"(b[1]));
}

// FMA-only exp(2*x) via 2^(x*2*log2e). Avoids MUFU. Rel err <= ~4e-6.
__device__ __forceinline__ float fast_exp2dot(float x) {
    float t  = x * 2.88539008177792681f;   // 2*log2(e)
    float fn = t + 12582912.0f;
    int   m  = __float_as_int(fn) - 0x4B400000;
    float r  = t - (fn - 12582912.0f);
    float p  = 1.3333558146e-3f;
    p = fmaf(p, r, 9.6181291e-3f);
    p = fmaf(p, r, 5.5504108664e-2f);
    p = fmaf(p, r, 2.4022650696e-1f);
    p = fmaf(p, r, 6.9314718056e-1f);
    p = fmaf(p, r, 1.0f);
    return __int_as_float(__float_as_int(p) + (m << 23));
}

// ---------------------------------------------------------------------------
// K1: L2-normalize rows of [emb_i; emb_j] -> bf16 g_repb. One block per row.
// Block 0 also zeroes the accumulators.
// ---------------------------------------------------------------------------
__global__ void normalize_kernel(const float* __restrict__ a,
                                 const float* __restrict__ b) {
    int row = blockIdx.x;
    int tid = threadIdx.x;  // 128
    if (row == 0 && tid == 0) { g_acc[0] = 0.0; g_acc[1] = 0.0; }

    const float* src = (row < HALF) ? (a + (size_t)row * D)
                                    : (b + (size_t)(row - HALF) * D);

    float4 v = reinterpret_cast<const float4*>(src)[tid];
    float ss = v.x * v.x + v.y * v.y + v.z * v.z + v.w * v.w;

    #pragma unroll
    for (int o = 16; o > 0; o >>= 1)
        ss += __shfl_xor_sync(0xFFFFFFFFu, ss, o);

    __shared__ float ws[4];
    int wid = tid >> 5, lane = tid & 31;
    if (lane == 0) ws[wid] = ss;
    __syncthreads();

    float total = ws[0] + ws[1] + ws[2] + ws[3];
    float inv = rsqrtf(fmaxf(total, 1e-24f));  // == x / max(norm, 1e-12)

    __nv_bfloat162 lo = __floats2bfloat162_rn(v.x * inv, v.y * inv);
    __nv_bfloat162 hi = __floats2bfloat162_rn(v.z * inv, v.w * inv);
    uint2 pk;
    pk.x = *reinterpret_cast<uint32_t*>(&lo);
    pk.y = *reinterpret_cast<uint32_t*>(&hi);
    reinterpret_cast<uint2*>(g_repb + (size_t)row * D)[tid] = pk;
}

// ---------------------------------------------------------------------------
// Stage loader: A = 128 rows, B = 256 rows, 128B per row, 16B chunks,
// XOR swizzle chunk' = chunk ^ (row & 7).
// ---------------------------------------------------------------------------
__device__ __forceinline__ void load_stage(uint32_t slot,
                                           const __nv_bfloat16* __restrict__ Ab,
                                           const __nv_bfloat16* __restrict__ Bb,
                                           int kk, int tid) {
    #pragma unroll
    for (int s = 0; s < 4; s++) {          // A: 1024 chunks
        int idx = tid + s * NT;
        int row = idx >> 3;
        int ch  = idx & 7;
        uint32_t dst = (uint32_t)(row * 128 + ((ch ^ (row & 7)) << 4));
        cp16(slot + dst, Ab + (size_t)row * D + kk + ch * 8);
    }
    #pragma unroll
    for (int s = 0; s < 8; s++) {          // B: 2048 chunks
        int idx = tid + s * NT;
        int row = idx >> 3;
        int ch  = idx & 7;
        uint32_t dst = (uint32_t)(row * 128 + ((ch ^ (row & 7)) << 4));
        cp16(slot + A_B + dst, Bb + (size_t)row * D + kk + ch * 8);
    }
}

// ---------------------------------------------------------------------------
// K2: bf16 mma.sync GEMM over 1056 upper-triangular 128x256 tiles, fused
// exp reduction + last-CTA finalize. 8 warps of 64x64, 4-stage ring.
// ---------------------------------------------------------------------------
__global__ __launch_bounds__(NT, 1)
void gemm_exp_kernel(float* __restrict__ out) {
    // Decode tile index -> (bi in 0..63 of 128 rows, cb in bi/2..31 of 256 cols)
    // Pair p = bi/2; tiles before pair p: C(p) = p*(65-p).
    int idx = blockIdx.x;
    int p   = (int)((65.0f - sqrtf(4225.0f - 4.0f * (float)idx)) * 0.5f);
    if (p > 31) p = 31;
    while (p * (65 - p) > idx) p--;
    while ((p + 1) * (64 - p) <= idx) p++;
    int rem = idx - p * (65 - p);
    int cnt = 32 - p;
    int bi  = 2 * p + (rem >= cnt ? 1 : 0);
    int cb  = p + (rem >= cnt ? rem - cnt : rem);

    extern __shared__ char sm[];
    uint32_t sbase = smem_u32(sm);

    const int tid    = threadIdx.x;
    const int wid    = tid >> 5;
    const int lane   = tid & 31;
    const int warp_m = wid & 1;      // 2 warps down M (64 rows each)
    const int warp_n = wid >> 1;     // 4 warps across N (64 cols each)

    const __nv_bfloat16* __restrict__ Ab = g_repb + (size_t)bi * TM_CTA * D;
    const __nv_bfloat16* __restrict__ Bb = g_repb + (size_t)cb * TN_CTA * D;

    float acc[4][8][4];   // [mf][nf][frag] — 64x64 warp tile
    #pragma unroll
    for (int mf = 0; mf < 4; mf++)
        #pragma unroll
        for (int nf = 0; nf < 8; nf++)
            #pragma unroll
            for (int e = 0; e < 4; e++)
                acc[mf][nf][e] = 0.0f;

    // Per-lane ldmatrix address components (swizzle-aware)
    const int a_row = lane & 15;
    const int a_hi  = lane >> 4;
    const int a_sw  = a_row & 7;
    const int b_n   = ((lane >> 4) << 3) + (lane & 7);
    const int b_hi  = (lane >> 3) & 1;
    const int b_sw  = b_n & 7;

    // Prologue: fill 3 of 4 ring slots
    load_stage(sbase,              Ab, Bb, 0,      tid); CP_COMMIT();
    load_stage(sbase + SLOT_B,     Ab, Bb, KC,     tid); CP_COMMIT();
    load_stage(sbase + 2 * SLOT_B, Ab, Bb, 2 * KC, tid); CP_COMMIT();

    #pragma unroll 1
    for (int j = 0; j < NCHUNK; j++) {
        if (j < NCHUNK - 2) CP_WAIT(2);
        else if (j == NCHUNK - 2) CP_WAIT(1);
        else CP_WAIT(0);
        __syncthreads();

        if (j + 3 < NCHUNK) {
            load_stage(sbase + (uint32_t)((j + 3) & 3) * SLOT_B,
                       Ab, Bb, (j + 3) * KC, tid);
            CP_COMMIT();
        }

        uint32_t sA = sbase + (uint32_t)(j & 3) * SLOT_B;
        uint32_t sB = sA + A_B;

        #pragma unroll
        for (int ks = 0; ks < 4; ks++) {
            uint32_t afr[4][4];
            #pragma unroll
            for (int mf = 0; mf < 4; mf++) {
                int grow = warp_m * 64 + mf * 16 + a_row;
                uint32_t ca = (uint32_t)((2 * ks + a_hi) ^ a_sw);
                ldmx4(afr[mf][0], afr[mf][1], afr[mf][2], afr[mf][3],
                      sA + grow * 128 + ca * 16);
            }
            uint32_t bfr[8][2];
            #pragma unroll
            for (int np = 0; np < 4; np++) {
                int gn = warp_n * 64 + np * 16 + b_n;
                uint32_t cbx = (uint32_t)((2 * ks + b_hi) ^ b_sw);
                uint32_t r0, r1, r2, r3;
                ldmx4(r0, r1, r2, r3, sB + gn * 128 + cbx * 16);
                bfr[2 * np][0] = r0;     bfr[2 * np][1] = r1;
                bfr[2 * np + 1][0] = r2; bfr[2 * np + 1][1] = r3;
            }
            #pragma unroll
            for (int mf = 0; mf < 4; mf++)
                #pragma unroll
                for (int nf = 0; nf < 8; nf++)
                    mma16816(acc[mf][nf], afr[mf], bfr[nf]);
        }
    }

    // Epilogue: per-element global (m, n); sum where n > m (x2 mirror),
    // nominator where n - m in {2048, 4096, 6144}.
    const int grp = lane >> 2;
    const int tig = lane & 3;
    const int mbase = bi * TM_CTA + warp_m * 64;
    const int nbase = cb * TN_CTA + warp_n * 64;

    float sum = 0.0f, nom = 0.0f;
    #pragma unroll
    for (int mf = 0; mf < 4; mf++) {
        #pragma unroll
        for (int nf = 0; nf < 8; nf++) {
            int m0 = mbase + mf * 16 + grp;
            int n0 = nbase + nf * 8 + tig * 2;
            #pragma unroll
            for (int e = 0; e < 4; e++) {
                int mm = m0 + (e >> 1) * 8;
                int nn = n0 + (e & 1);
                float ex = fast_exp2dot(acc[mf][nf][e]);
                int dnm = nn - mm;
                if (dnm > 0) sum += ex;
                if ((dnm == 2048) | (dnm == 4096) | (dnm == 6144)) nom += ex;
            }
        }
    }

    // Block reduction -> one double atomic per tile (reuse stage smem)
    __syncthreads();
    float2* red = reinterpret_cast<float2*>(sm);
    red[tid] = make_float2(sum, nom);
    __syncthreads();
    #pragma unroll
    for (int s2 = NT / 2; s2 >= 32; s2 >>= 1) {
        if (tid < s2) {
            float2 o = red[tid + s2];
            red[tid].x += o.x;
            red[tid].y += o.y;
        }
        __syncthreads();
    }
    if (tid < 32) {
        float2 v2 = red[tid];
        #pragma unroll
        for (int o = 16; o > 0; o >>= 1) {
            v2.x += __shfl_xor_sync(0xFFFFFFFFu, v2.x, o);
            v2.y += __shfl_xor_sync(0xFFFFFFFFu, v2.y, o);
        }
        if (tid == 0) {
            atomicAdd(&g_acc[0], 2.0 * (double)v2.x);   // mirror lower triangle
            if (v2.y != 0.0f) atomicAdd(&g_acc[1], 2.0 * (double)v2.y);

            // Last-CTA finalize
            __threadfence();
            unsigned int t = atomicAdd(&g_done, 1u);
            if (t == NTILES - 1) {
                __threadfence();
                double nomv = g_acc[1];
                double den  = g_acc[0] - nomv;
                out[0] = (float)(-log(nomv / den) / (double)NROWS);
                g_done = 0;   // reset for next graph replay
            }
        }
    }
}

// ---------------------------------------------------------------------------
// Entry point
// ---------------------------------------------------------------------------
extern "C" void kernel_launch(void* const* d_in, const int* in_sizes, int n_in,
                              void* d_out, int out_size) {
    const float* emb_i = (const float*)d_in[0];
    const float* emb_j = (const float*)d_in[1];
    float* out = (float*)d_out;

    cudaFuncSetAttribute(gemm_exp_kernel,
                         cudaFuncAttributeMaxDynamicSharedMemorySize, SMEM_DYN);

    normalize_kernel<<<NROWS, 128>>>(emb_i, emb_j);
    gemm_exp_kernel<<<NTILES, NT, SMEM_DYN>>>(out);
}

// round 7
// speedup vs baseline: 1.1419x; 1.1385x over previous
#include <cuda_runtime.h>
#include <cuda_bf16.h>
#include <math.h>
#include <cstdint>

// ---------------------------------------------------------------------------
// Problem constants
// ---------------------------------------------------------------------------
#define NROWS 8192       // 4B rows in rep
#define HALF  4096       // rows per input
#define D     512        // embedding dim

// GEMM config: 128x128 CTA tile, 8 warps of 64x32, K chunked by 64 bf16
#define TILE    128
#define KC      64
#define NCHUNK  (D / KC)           // 8
#define NT      256
#define NSTAGE  3
#define STAGE_B (TILE * KC * 2)    // 16384 bytes per operand per stage
#define SLOT_B  (2 * STAGE_B)      // A + B per stage
#define SMEM_DYN (NSTAGE * SLOT_B) // 96 KB -> 2 CTAs/SM

#define NTILES  2080               // 64*65/2 upper-triangular 128x128 tiles

// ---------------------------------------------------------------------------
// Static scratch
// ---------------------------------------------------------------------------
__device__ __align__(16) __nv_bfloat16 g_repb[(size_t)NROWS * D];  // 8 MB
__device__ double g_acc[2];        // [0] = S_offdiag (x2), [1] = nominator
__device__ unsigned int g_done;    // CTA arrival counter (self-resetting)

// ---------------------------------------------------------------------------
// Helpers
// ---------------------------------------------------------------------------
__device__ __forceinline__ uint32_t smem_u32(const void* p) {
    uint32_t a;
    asm("{ .reg .u64 t; cvta.to.shared.u64 t, %1; cvt.u32.u64 %0, t; }"
        : "=r"(a) : "l"(p));
    return a;
}

__device__ __forceinline__ void cp16(uint32_t dst, const void* src) {
    asm volatile("cp.async.cg.shared.global [%0], [%1], 16;"
                 :: "r"(dst), "l"(src));
}
#define CP_COMMIT() asm volatile("cp.async.commit_group;" ::: "memory")
#define CP_WAIT(n)  asm volatile("cp.async.wait_group %0;" :: "n"(n) : "memory")

__device__ __forceinline__ void ldmx4(uint32_t& r0, uint32_t& r1,
                                      uint32_t& r2, uint32_t& r3, uint32_t a) {
    asm volatile("ldmatrix.sync.aligned.m8n8.x4.shared.b16 {%0,%1,%2,%3}, [%4];"
                 : "=r"(r0), "=r"(r1), "=r"(r2), "=r"(r3) : "r"(a));
}

__device__ __forceinline__ void mma16816(float* c, const uint32_t* a,
                                         const uint32_t* b) {
    asm volatile(
        "mma.sync.aligned.m16n8k16.row.col.f32.bf16.bf16.f32 "
        "{%0,%1,%2,%3}, {%4,%5,%6,%7}, {%8,%9}, {%0,%1,%2,%3};"
        : "+f"(c[0]), "+f"(c[1]), "+f"(c[2]), "+f"(c[3])
        : "r"(a[0]), "r"(a[1]), "r"(a[2]), "r"(a[3]), "r"(b[0]), "r"(b[1]));
}

// FMA-only exp(2*x) via 2^(x*2*log2e). Avoids MUFU. Rel err <= ~4e-6.
__device__ __forceinline__ float fast_exp2dot(float x) {
    float t  = x * 2.88539008177792681f;   // 2*log2(e)
    float fn = t + 12582912.0f;
    int   m  = __float_as_int(fn) - 0x4B400000;
    float r  = t - (fn - 12582912.0f);
    float p  = 1.3333558146e-3f;
    p = fmaf(p, r, 9.6181291e-3f);
    p = fmaf(p, r, 5.5504108664e-2f);
    p = fmaf(p, r, 2.4022650696e-1f);
    p = fmaf(p, r, 6.9314718056e-1f);
    p = fmaf(p, r, 1.0f);
    return __int_as_float(__float_as_int(p) + (m << 23));
}

// ---------------------------------------------------------------------------
// K1: L2-normalize rows of [emb_i; emb_j] -> bf16 g_repb. One block per row.
// Block 0 also zeroes the accumulators.
// ---------------------------------------------------------------------------
__global__ void normalize_kernel(const float* __restrict__ a,
                                 const float* __restrict__ b) {
    int row = blockIdx.x;
    int tid = threadIdx.x;  // 128
    if (row == 0 && tid == 0) { g_acc[0] = 0.0; g_acc[1] = 0.0; }

    const float* src = (row < HALF) ? (a + (size_t)row * D)
                                    : (b + (size_t)(row - HALF) * D);

    float4 v = reinterpret_cast<const float4*>(src)[tid];
    float ss = v.x * v.x + v.y * v.y + v.z * v.z + v.w * v.w;

    #pragma unroll
    for (int o = 16; o > 0; o >>= 1)
        ss += __shfl_xor_sync(0xFFFFFFFFu, ss, o);

    __shared__ float ws[4];
    int wid = tid >> 5, lane = tid & 31;
    if (lane == 0) ws[wid] = ss;
    __syncthreads();

    float total = ws[0] + ws[1] + ws[2] + ws[3];
    float inv = rsqrtf(fmaxf(total, 1e-24f));  // == x / max(norm, 1e-12)

    __nv_bfloat162 lo = __floats2bfloat162_rn(v.x * inv, v.y * inv);
    __nv_bfloat162 hi = __floats2bfloat162_rn(v.z * inv, v.w * inv);
    uint2 pk;
    pk.x = *reinterpret_cast<uint32_t*>(&lo);
    pk.y = *reinterpret_cast<uint32_t*>(&hi);
    reinterpret_cast<uint2*>(g_repb + (size_t)row * D)[tid] = pk;
}

// ---------------------------------------------------------------------------
// Stage loader: 128 rows x 128B per operand, 16B chunks, XOR swizzle
// chunk' = chunk ^ (row & 7).
// ---------------------------------------------------------------------------
__device__ __forceinline__ void load_stage(uint32_t sA, uint32_t sB,
                                           const __nv_bfloat16* __restrict__ Ab,
                                           const __nv_bfloat16* __restrict__ Bb,
                                           int kk, int tid) {
    #pragma unroll
    for (int s = 0; s < 4; s++) {
        int idx = tid + s * NT;          // 0..1023
        int row = idx >> 3;              // 0..127
        int ch  = idx & 7;               // 16B chunk in 128B row
        uint32_t dst = (uint32_t)(row * 128 + ((ch ^ (row & 7)) << 4));
        cp16(sA + dst, Ab + (size_t)row * D + kk + ch * 8);
        cp16(sB + dst, Bb + (size_t)row * D + kk + ch * 8);
    }
}

// ---------------------------------------------------------------------------
// K2: bf16 mma.sync GEMM over 2080 upper-triangular tiles, fused exp
// reduction + last-CTA finalize. Warps walk k-steps in rotated order so
// LDSM (crossbar) and HMMA (tensor) phases overlap across warps.
// ---------------------------------------------------------------------------
__global__ __launch_bounds__(NT, 2)
void gemm_exp_kernel(float* __restrict__ out) {
    // Decode linear tile index -> (bi, bj), bj >= bi.
    int idx = blockIdx.x;
    int bi  = (int)((129.0f - sqrtf(16641.0f - 8.0f * (float)idx)) * 0.5f);
    if (bi > 63) bi = 63;
    while (bi * (129 - bi) / 2 > idx) bi--;
    while ((bi + 1) * (129 - (bi + 1)) / 2 <= idx) bi++;
    int bj = bi + (idx - bi * (129 - bi) / 2);

    extern __shared__ char sm[];
    uint32_t sbase = smem_u32(sm);

    const int tid    = threadIdx.x;
    const int wid    = tid >> 5;
    const int lane   = tid & 31;
    const int warp_m = wid & 1;      // 2 warps down M (64 rows each)
    const int warp_n = wid >> 1;     // 4 warps across N (32 cols each)

    const __nv_bfloat16* __restrict__ Ab = g_repb + (size_t)bi * TILE * D;
    const __nv_bfloat16* __restrict__ Bb = g_repb + (size_t)bj * TILE * D;

    float acc[4][4][4];   // [mf][nf][frag]
    #pragma unroll
    for (int mf = 0; mf < 4; mf++)
        #pragma unroll
        for (int nf = 0; nf < 4; nf++)
            #pragma unroll
            for (int e = 0; e < 4; e++)
                acc[mf][nf][e] = 0.0f;

    // Per-lane ldmatrix address components (swizzle-aware)
    const int a_row = lane & 15;
    const int a_hi  = lane >> 4;
    const int a_sw  = a_row & 7;
    const int b_n   = ((lane >> 4) << 3) + (lane & 7);
    const int b_hi  = (lane >> 3) & 1;
    const int b_sw  = b_n & 7;

    // Prologue: fill first two ring slots
    load_stage(sbase,          sbase + STAGE_B,          Ab, Bb, 0,  tid);
    CP_COMMIT();
    load_stage(sbase + SLOT_B, sbase + SLOT_B + STAGE_B, Ab, Bb, KC, tid);
    CP_COMMIT();

    #pragma unroll 1
    for (int j = 0; j < NCHUNK; j++) {
        if (j < NCHUNK - 1) CP_WAIT(1); else CP_WAIT(0);
        __syncthreads();

        if (j + 2 < NCHUNK) {
            uint32_t sl = sbase + (uint32_t)((j + 2) % NSTAGE) * SLOT_B;
            load_stage(sl, sl + STAGE_B, Ab, Bb, (j + 2) * KC, tid);
            CP_COMMIT();
        }

        uint32_t sA = sbase + (uint32_t)(j % NSTAGE) * SLOT_B;
        uint32_t sB = sA + STAGE_B;

        #pragma unroll
        for (int kx = 0; kx < 4; kx++) {
            // Rotated k-step order: warps de-phase so crossbar and tensor
            // pipes run concurrently instead of alternating in lockstep.
            int ks = (kx + wid) & 3;

            uint32_t afr[4][4];
            #pragma unroll
            for (int mf = 0; mf < 4; mf++) {
                int grow = warp_m * 64 + mf * 16 + a_row;
                uint32_t ca = (uint32_t)((2 * ks + a_hi) ^ a_sw);
                ldmx4(afr[mf][0], afr[mf][1], afr[mf][2], afr[mf][3],
                      sA + grow * 128 + ca * 16);
            }
            uint32_t bfr[4][2];
            #pragma unroll
            for (int np = 0; np < 2; np++) {
                int gn = warp_n * 32 + np * 16 + b_n;
                uint32_t cb = (uint32_t)((2 * ks + b_hi) ^ b_sw);
                uint32_t r0, r1, r2, r3;
                ldmx4(r0, r1, r2, r3, sB + gn * 128 + cb * 16);
                bfr[2 * np][0] = r0;     bfr[2 * np][1] = r1;
                bfr[2 * np + 1][0] = r2; bfr[2 * np + 1][1] = r3;
            }
            #pragma unroll
            for (int mf = 0; mf < 4; mf++)
                #pragma unroll
                for (int nf = 0; nf < 4; nf++)
                    mma16816(acc[mf][nf], afr[mf], bfr[nf]);
        }
    }

    // Epilogue: exp(2*dot) + masked sums directly from register fragments.
    const bool diag = (bi == bj);
    const int  dbj  = bj - bi;
    const bool nomt = (dbj == 16) | (dbj == 32) | (dbj == 48);
    const int  grp  = lane >> 2;
    const int  tig  = lane & 3;

    float sum = 0.0f, nom = 0.0f;
    #pragma unroll
    for (int mf = 0; mf < 4; mf++) {
        #pragma unroll
        for (int nf = 0; nf < 4; nf++) {
            int m0 = warp_m * 64 + mf * 16 + grp;
            int n0 = warp_n * 32 + nf * 8 + tig * 2;
            #pragma unroll
            for (int e = 0; e < 4; e++) {
                int mm = m0 + (e >> 1) * 8;
                int nn = n0 + (e & 1);
                float ex = fast_exp2dot(acc[mf][nf][e]);
                if (!diag || nn > mm) sum += ex;
                if (nomt & (nn == mm)) nom += ex;
            }
        }
    }

    // Flat reduction: shfl within warp, 8 partials in smem, one barrier,
    // warp 0 finishes -> 2 double atomics per CTA.
    #pragma unroll
    for (int o = 16; o > 0; o >>= 1) {
        sum += __shfl_xor_sync(0xFFFFFFFFu, sum, o);
        nom += __shfl_xor_sync(0xFFFFFFFFu, nom, o);
    }
    __syncthreads();  // mainloop smem reads complete before overlay write
    float2* wred = reinterpret_cast<float2*>(sm);
    if (lane == 0) wred[wid] = make_float2(sum, nom);
    __syncthreads();
    if (wid == 0) {
        float2 v2 = (lane < 8) ? wred[lane] : make_float2(0.0f, 0.0f);
        #pragma unroll
        for (int o = 4; o > 0; o >>= 1) {
            v2.x += __shfl_xor_sync(0xFFFFFFFFu, v2.x, o);
            v2.y += __shfl_xor_sync(0xFFFFFFFFu, v2.y, o);
        }
        if (lane == 0) {
            atomicAdd(&g_acc[0], 2.0 * (double)v2.x);   // mirror lower triangle
            if (v2.y != 0.0f) atomicAdd(&g_acc[1], 2.0 * (double)v2.y);

            // Last-CTA finalize
            __threadfence();
            unsigned int t = atomicAdd(&g_done, 1u);
            if (t == NTILES - 1) {
                __threadfence();
                double nomv = g_acc[1];
                double den  = g_acc[0] - nomv;
                out[0] = (float)(-log(nomv / den) / (double)NROWS);
                g_done = 0;   // reset for next graph replay
            }
        }
    }
}

// ---------------------------------------------------------------------------
// Entry point
// ---------------------------------------------------------------------------
extern "C" void kernel_launch(void* const* d_in, const int* in_sizes, int n_in,
                              void* d_out, int out_size) {
    const float* emb_i = (const float*)d_in[0];
    const float* emb_j = (const float*)d_in[1];
    float* out = (float*)d_out;

    cudaFuncSetAttribute(gemm_exp_kernel,
                         cudaFuncAttributeMaxDynamicSharedMemorySize, SMEM_DYN);

    normalize_kernel<<<NROWS, 128>>>(emb_i, emb_j);
    gemm_exp_kernel<<<NTILES, NT, SMEM_DYN>>>(out);
}